// round 1
// baseline (speedup 1.0000x reference)
#include <cuda_runtime.h>

#define NJ 23
#define NP 16

// Packed A' matrices written by pose_kernel, read by lbs_kernel.
// Layout: [((j*4+k)*3+i)*16 + p]  (j=joint, k=input component x/y/z/1, i=output coord, p=pose)
// 16 consecutive poses per (j,k,i) -> 64B aligned runs -> LDS.128 of pose-quads.
__device__ __align__(16) float d_Apacked[NJ * 4 * 3 * NP];

__constant__ int c_parents[NJ] = {-1,0,1,1,3,4,5,4,7,4,9,1,11,12,13,12,15,12,17,0,19,0,21};

// ---------------------------------------------------------------------------
// Kernel 1: pose chain (tiny). One thread per pose.
// ---------------------------------------------------------------------------
__global__ void pose_kernel(const float* __restrict__ joints,
                            const float* __restrict__ displacement,
                            const float* __restrict__ random_dis,
                            const float* __restrict__ jp0,  const float* __restrict__ jp3,
                            const float* __restrict__ jp4,  const float* __restrict__ jp5,
                            const float* __restrict__ jp7,  const float* __restrict__ jp9,
                            const float* __restrict__ jp11, const float* __restrict__ jp12,
                            const float* __restrict__ jp13, const float* __restrict__ jp15,
                            const float* __restrict__ jp17,
                            float* __restrict__ out_joints)
{
    int p = threadIdx.x;
    if (p >= NP) return;

    const float Q = 0.78539816339744831f;   // pi/4
    const float H = 1.57079632679489662f;   // pi/2
    const int   slots[11]  = {0,3,4,5,7,9,11,12,13,15,17};
    const float scales[11] = {Q,H,H,Q,Q,Q,H,H,Q,Q,Q};
    const float* prm[11] = {jp0,jp3,jp4,jp5,jp7,jp9,jp11,jp12,jp13,jp15,jp17};

    float pose[NJ][3];
    for (int jt = 0; jt < NJ; jt++) { pose[jt][0] = 0.f; pose[jt][1] = 0.f; pose[jt][2] = 0.f; }
    for (int s = 0; s < 11; s++)
        for (int k = 0; k < 3; k++)
            pose[slots[s]][k] = scales[s] * tanhf(prm[s][p*3 + k]);

    float shift[3];
    for (int k = 0; k < 3; k++)
        shift[k] = random_dis[p*3 + k] + 3.0f * tanhf(displacement[p*3 + k]);

    float GR[NJ][9], Gt[NJ][3];

    for (int jt = 0; jt < NJ; jt++) {
        // Rodrigues
        float rx = pose[jt][0], ry = pose[jt][1], rz = pose[jt][2];
        float ang = sqrtf(rx*rx + ry*ry + rz*rz + 1e-16f);
        float x = rx/ang, y = ry/ang, z = rz/ang;
        float sn = sinf(ang), cs = cosf(ang), t = 1.0f - cs;
        float R[9];
        R[0] = 1.0f - t*(y*y + z*z); R[1] = -sn*z + t*x*y;        R[2] =  sn*y + t*x*z;
        R[3] =  sn*z + t*x*y;        R[4] = 1.0f - t*(x*x + z*z); R[5] = -sn*x + t*y*z;
        R[6] = -sn*y + t*x*z;        R[7] =  sn*x + t*y*z;        R[8] = 1.0f - t*(x*x + y*y);

        int par = c_parents[jt];
        float rel[3];
        if (par < 0) {
            rel[0] = joints[0]; rel[1] = joints[1]; rel[2] = joints[2];
        } else {
            rel[0] = joints[jt*3+0] - joints[par*3+0];
            rel[1] = joints[jt*3+1] - joints[par*3+1];
            rel[2] = joints[jt*3+2] - joints[par*3+2];
        }

        if (par < 0) {
            for (int i = 0; i < 9; i++) GR[jt][i] = R[i];
            for (int i = 0; i < 3; i++) Gt[jt][i] = rel[i];
        } else {
            for (int i = 0; i < 3; i++) {
                for (int k = 0; k < 3; k++) {
                    GR[jt][i*3+k] = GR[par][i*3+0]*R[0*3+k]
                                  + GR[par][i*3+1]*R[1*3+k]
                                  + GR[par][i*3+2]*R[2*3+k];
                }
                Gt[jt][i] = GR[par][i*3+0]*rel[0] + GR[par][i*3+1]*rel[1]
                          + GR[par][i*3+2]*rel[2] + Gt[par][i];
            }
        }

        float jx = joints[jt*3+0], jy = joints[jt*3+1], jz = joints[jt*3+2];
        for (int i = 0; i < 3; i++) {
            out_joints[(p*NJ + jt)*3 + i] = Gt[jt][i] + shift[i];
            // A' translation: G.t - G.R@j + shift  (shift folded; Σ_j w_j = 1)
            float At = Gt[jt][i]
                     - (GR[jt][i*3+0]*jx + GR[jt][i*3+1]*jy + GR[jt][i*3+2]*jz)
                     + shift[i];
            d_Apacked[((jt*4 + 0)*3 + i)*NP + p] = GR[jt][i*3+0];
            d_Apacked[((jt*4 + 1)*3 + i)*NP + p] = GR[jt][i*3+1];
            d_Apacked[((jt*4 + 2)*3 + i)*NP + p] = GR[jt][i*3+2];
            d_Apacked[((jt*4 + 3)*3 + i)*NP + p] = At;
        }
    }
}

// ---------------------------------------------------------------------------
// f32x2 packed helpers (SASS FFMA2 — only reachable via PTX)
// ---------------------------------------------------------------------------
__device__ __forceinline__ unsigned long long pack2(float a) {
    unsigned long long r;
    asm("mov.b64 %0, {%1, %1};" : "=l"(r) : "f"(a));
    return r;
}
__device__ __forceinline__ void fma2(unsigned long long& d, unsigned long long a, unsigned long long b) {
    asm("fma.rn.f32x2 %0, %1, %2, %0;" : "+l"(d) : "l"(a), "l"(b));
}
__device__ __forceinline__ void unpack2(unsigned long long v, float& a, float& b) {
    asm("mov.b64 {%0, %1}, %2;" : "=f"(a), "=f"(b) : "l"(v));
}

// ---------------------------------------------------------------------------
// Kernel 2: vertex skinning. One thread per vertex, 16 poses in 8 f32x2 lanes.
// ---------------------------------------------------------------------------
__global__ void __launch_bounds__(256, 2)
lbs_kernel(const float* __restrict__ verts,
           const float* __restrict__ weights,
           float* __restrict__ out, int V)
{
    __shared__ __align__(16) float sA[NJ * 4 * 3 * NP];   // 17664 B
    for (int t = threadIdx.x; t < NJ*4*3*NP; t += 256) sA[t] = d_Apacked[t];
    __syncthreads();

    int v = blockIdx.x * 256 + threadIdx.x;
    if (v >= V) return;

    float vx = verts[3*v + 0];
    float vy = verts[3*v + 1];
    float vz = verts[3*v + 2];

    // Preload all 23 weights (high MLP; latency overlapped across warps)
    float w[NJ];
    const float* wp = weights + (size_t)v * NJ;
#pragma unroll
    for (int j = 0; j < NJ; j++) w[j] = wp[j];

    // Accumulators: acc[i][q] holds output coord i for poses (2q, 2q+1)
    unsigned long long acc[3][8];
#pragma unroll
    for (int i = 0; i < 3; i++)
#pragma unroll
        for (int q = 0; q < 8; q++) acc[i][q] = 0ull;

#pragma unroll
    for (int j = 0; j < NJ; j++) {
        float wj = w[j];
        unsigned long long m[4];
        m[0] = pack2(wj * vx);
        m[1] = pack2(wj * vy);
        m[2] = pack2(wj * vz);
        m[3] = pack2(wj);
#pragma unroll
        for (int k = 0; k < 4; k++) {
#pragma unroll
            for (int i = 0; i < 3; i++) {
                const ulonglong2* pA = (const ulonglong2*)(sA + ((j*4 + k)*3 + i)*NP);
#pragma unroll
                for (int q2 = 0; q2 < 4; q2++) {
                    ulonglong2 u = pA[q2];            // LDS.128 broadcast, 4 poses
                    fma2(acc[i][2*q2 + 0], u.x, m[k]);
                    fma2(acc[i][2*q2 + 1], u.y, m[k]);
                }
            }
        }
    }

    // Store: per pose, 3 consecutive floats; consecutive vertices -> coalesced.
#pragma unroll
    for (int q = 0; q < 8; q++) {
        float a0x, a0y, a1x, a1y, a2x, a2y;
        unpack2(acc[0][q], a0x, a0y);
        unpack2(acc[1][q], a1x, a1y);
        unpack2(acc[2][q], a2x, a2y);
        size_t b0 = ((size_t)(2*q + 0) * V + v) * 3;
        out[b0 + 0] = a0x; out[b0 + 1] = a1x; out[b0 + 2] = a2x;
        size_t b1 = ((size_t)(2*q + 1) * V + v) * 3;
        out[b1 + 0] = a0y; out[b1 + 1] = a1y; out[b1 + 2] = a2y;
    }
}

// ---------------------------------------------------------------------------
extern "C" void kernel_launch(void* const* d_in, const int* in_sizes, int n_in,
                              void* d_out, int out_size)
{
    const float* verts   = (const float*)d_in[0];   // (1, V, 3)
    const float* joints  = (const float*)d_in[1];   // (1, 23, 3)
    const float* weights = (const float*)d_in[2];   // (V, 23)
    const float* disp    = (const float*)d_in[3];   // (P, 1, 3)
    const float* rdis    = (const float*)d_in[4];   // (P, 3)

    int V = in_sizes[0] / 3;
    float* out = (float*)d_out;
    // posed_joints segment sits at the tail: out_size - P*J*3
    float* out_joints = out + (size_t)out_size - (size_t)NP * NJ * 3;

    pose_kernel<<<1, 32>>>(joints, disp, rdis,
                           (const float*)d_in[5],  (const float*)d_in[6],
                           (const float*)d_in[7],  (const float*)d_in[8],
                           (const float*)d_in[9],  (const float*)d_in[10],
                           (const float*)d_in[11], (const float*)d_in[12],
                           (const float*)d_in[13], (const float*)d_in[14],
                           (const float*)d_in[15],
                           out_joints);

    int blocks = (V + 255) / 256;
    lbs_kernel<<<blocks, 256>>>(verts, weights, out, V);
}

// round 2
// speedup vs baseline: 1.8661x; 1.8661x over previous
#include <cuda_runtime.h>

#define NJ 23
#define NP 16
#define WROW 260   // padded row stride for transposed weights (multiple of 4, 16B-aligned rows)

// Packed A' matrices written by pose_kernel, read by lbs_kernel.
// Layout: [((j*4+k)*3+i)*16 + p]  (j=joint, k=input comp x/y/z/1, i=out coord, p=pose)
__device__ __align__(16) float d_Apacked[NJ * 4 * 3 * NP];

__constant__ int c_parents[NJ] = {-1,0,1,1,3,4,5,4,7,4,9,1,11,12,13,12,15,12,17,0,19,0,21};

// ---------------------------------------------------------------------------
// Kernel 1: pose chain (tiny). One thread per pose.
// ---------------------------------------------------------------------------
__global__ void pose_kernel(const float* __restrict__ joints,
                            const float* __restrict__ displacement,
                            const float* __restrict__ random_dis,
                            const float* __restrict__ jp0,  const float* __restrict__ jp3,
                            const float* __restrict__ jp4,  const float* __restrict__ jp5,
                            const float* __restrict__ jp7,  const float* __restrict__ jp9,
                            const float* __restrict__ jp11, const float* __restrict__ jp12,
                            const float* __restrict__ jp13, const float* __restrict__ jp15,
                            const float* __restrict__ jp17,
                            float* __restrict__ out_joints)
{
    int p = threadIdx.x;
    if (p >= NP) return;

    const float Q = 0.78539816339744831f;   // pi/4
    const float H = 1.57079632679489662f;   // pi/2
    const int   slots[11]  = {0,3,4,5,7,9,11,12,13,15,17};
    const float scales[11] = {Q,H,H,Q,Q,Q,H,H,Q,Q,Q};
    const float* prm[11] = {jp0,jp3,jp4,jp5,jp7,jp9,jp11,jp12,jp13,jp15,jp17};

    float pose[NJ][3];
    for (int jt = 0; jt < NJ; jt++) { pose[jt][0] = 0.f; pose[jt][1] = 0.f; pose[jt][2] = 0.f; }
    for (int s = 0; s < 11; s++)
        for (int k = 0; k < 3; k++)
            pose[slots[s]][k] = scales[s] * tanhf(prm[s][p*3 + k]);

    float shift[3];
    for (int k = 0; k < 3; k++)
        shift[k] = random_dis[p*3 + k] + 3.0f * tanhf(displacement[p*3 + k]);

    float GR[NJ][9], Gt[NJ][3];

    for (int jt = 0; jt < NJ; jt++) {
        float rx = pose[jt][0], ry = pose[jt][1], rz = pose[jt][2];
        float ang = sqrtf(rx*rx + ry*ry + rz*rz + 1e-16f);
        float x = rx/ang, y = ry/ang, z = rz/ang;
        float sn = sinf(ang), cs = cosf(ang), t = 1.0f - cs;
        float R[9];
        R[0] = 1.0f - t*(y*y + z*z); R[1] = -sn*z + t*x*y;        R[2] =  sn*y + t*x*z;
        R[3] =  sn*z + t*x*y;        R[4] = 1.0f - t*(x*x + z*z); R[5] = -sn*x + t*y*z;
        R[6] = -sn*y + t*x*z;        R[7] =  sn*x + t*y*z;        R[8] = 1.0f - t*(x*x + y*y);

        int par = c_parents[jt];
        float rel[3];
        if (par < 0) {
            rel[0] = joints[0]; rel[1] = joints[1]; rel[2] = joints[2];
        } else {
            rel[0] = joints[jt*3+0] - joints[par*3+0];
            rel[1] = joints[jt*3+1] - joints[par*3+1];
            rel[2] = joints[jt*3+2] - joints[par*3+2];
        }

        if (par < 0) {
            for (int i = 0; i < 9; i++) GR[jt][i] = R[i];
            for (int i = 0; i < 3; i++) Gt[jt][i] = rel[i];
        } else {
            for (int i = 0; i < 3; i++) {
                for (int k = 0; k < 3; k++) {
                    GR[jt][i*3+k] = GR[par][i*3+0]*R[0*3+k]
                                  + GR[par][i*3+1]*R[1*3+k]
                                  + GR[par][i*3+2]*R[2*3+k];
                }
                Gt[jt][i] = GR[par][i*3+0]*rel[0] + GR[par][i*3+1]*rel[1]
                          + GR[par][i*3+2]*rel[2] + Gt[par][i];
            }
        }

        float jx = joints[jt*3+0], jy = joints[jt*3+1], jz = joints[jt*3+2];
        for (int i = 0; i < 3; i++) {
            out_joints[(p*NJ + jt)*3 + i] = Gt[jt][i] + shift[i];
            float At = Gt[jt][i]
                     - (GR[jt][i*3+0]*jx + GR[jt][i*3+1]*jy + GR[jt][i*3+2]*jz)
                     + shift[i];
            d_Apacked[((jt*4 + 0)*3 + i)*NP + p] = GR[jt][i*3+0];
            d_Apacked[((jt*4 + 1)*3 + i)*NP + p] = GR[jt][i*3+1];
            d_Apacked[((jt*4 + 2)*3 + i)*NP + p] = GR[jt][i*3+2];
            d_Apacked[((jt*4 + 3)*3 + i)*NP + p] = At;
        }
    }
}

// ---------------------------------------------------------------------------
// f32x2 packed helpers (SASS FFMA2 — only reachable via PTX)
// ---------------------------------------------------------------------------
__device__ __forceinline__ unsigned long long pack2(float a) {
    unsigned long long r;
    asm("mov.b64 %0, {%1, %1};" : "=l"(r) : "f"(a));
    return r;
}
__device__ __forceinline__ void fma2(unsigned long long& d, unsigned long long a, unsigned long long b) {
    asm("fma.rn.f32x2 %0, %1, %2, %0;" : "+l"(d) : "l"(a), "l"(b));
}
__device__ __forceinline__ void unpack2(unsigned long long v, float& a, float& b) {
    asm("mov.b64 {%0, %1}, %2;" : "=f"(a), "=f"(b) : "l"(v));
}

// ---------------------------------------------------------------------------
// Kernel 2: vertex skinning. Each thread: 4 vertices x 4 poses.
// tid%4 = pose group (poses 4*pg..4*pg+3), tid/4 = vertex quad within block.
// Block covers 256 vertices. A-slice LDS amortized over 4 vertices.
// ---------------------------------------------------------------------------
__global__ void __launch_bounds__(256)
lbs_kernel(const float* __restrict__ verts,
           const float* __restrict__ weights,
           float* __restrict__ out, int V)
{
    __shared__ __align__(16) float sA[NJ * 4 * 3 * NP];   // 17664 B
    __shared__ __align__(16) float sW[NJ * WROW];         // 23920 B, transposed [j][v]

    int tid = threadIdx.x;

    // Stage A (float4, coalesced/broadcast)
    for (int t = tid; t < NJ*4*3*NP/4; t += 256)
        ((float4*)sA)[t] = ((const float4*)d_Apacked)[t];

    // Stage weights transposed: sW[j][v] = weights[vbase+v][j]. Gmem read coalesced.
    int vbase = blockIdx.x * 256;
    int nv = V - vbase; if (nv > 256) nv = 256;
    for (int t = tid; t < nv * NJ; t += 256) {
        int v = t / NJ;
        int j = t - v * NJ;
        sW[j * WROW + v] = weights[(size_t)vbase * NJ + t];
    }
    __syncthreads();

    int pg  = tid & 3;        // pose group
    int vt  = tid >> 2;       // vertex quad index 0..63
    int v0l = vt * 4;         // local vertex base
    int v0  = vbase + v0l;
    if (v0 >= V) return;      // no syncs past this point
    bool full = (v0 + 3 < V);

    // Load 4 vertices (12 contiguous floats -> 3 LDG.128 when aligned)
    float vX[4], vY[4], vZ[4];
    if (full) {
        const float4* vp = (const float4*)(verts + (size_t)v0 * 3);
        float4 a = vp[0], b = vp[1], c = vp[2];
        vX[0]=a.x; vY[0]=a.y; vZ[0]=a.z;
        vX[1]=a.w; vY[1]=b.x; vZ[1]=b.y;
        vX[2]=b.z; vY[2]=b.w; vZ[2]=c.x;
        vX[3]=c.y; vY[3]=c.z; vZ[3]=c.w;
    } else {
#pragma unroll
        for (int v = 0; v < 4; v++) {
            if (v0 + v < V) {
                vX[v] = verts[(size_t)(v0+v)*3 + 0];
                vY[v] = verts[(size_t)(v0+v)*3 + 1];
                vZ[v] = verts[(size_t)(v0+v)*3 + 2];
            } else { vX[v]=0.f; vY[v]=0.f; vZ[v]=0.f; }
        }
    }

    // acc[v][i][q]: output coord i of vertex v for poses (4pg+2q, 4pg+2q+1)
    unsigned long long acc[4][3][2];
#pragma unroll
    for (int v = 0; v < 4; v++)
#pragma unroll
        for (int i = 0; i < 3; i++) { acc[v][i][0] = 0ull; acc[v][i][1] = 0ull; }

    for (int j = 0; j < NJ; j++) {
        float4 w4 = *(const float4*)(sW + j * WROW + v0l);  // weights of the 4 verts
        float wv[4] = {w4.x, w4.y, w4.z, w4.w};
        const float* Aj = sA + j * 4 * 3 * NP + pg * 4;

#pragma unroll
        for (int k = 0; k < 4; k++) {
            unsigned long long m[4];
#pragma unroll
            for (int v = 0; v < 4; v++) {
                float s = (k == 0) ? wv[v] * vX[v]
                        : (k == 1) ? wv[v] * vY[v]
                        : (k == 2) ? wv[v] * vZ[v]
                                   : wv[v];
                m[v] = pack2(s);
            }
#pragma unroll
            for (int i = 0; i < 3; i++) {
                ulonglong2 u = *(const ulonglong2*)(Aj + (k*3 + i) * NP);  // 4 poses of A
#pragma unroll
                for (int v = 0; v < 4; v++) {
                    fma2(acc[v][i][0], u.x, m[v]);
                    fma2(acc[v][i][1], u.y, m[v]);
                }
            }
        }
    }

    // Stores: per pose, 12 contiguous floats (4 verts x 3 coords) -> 3 STG.128
    bool vec = full && ((V & 3) == 0);
#pragma unroll
    for (int q = 0; q < 2; q++) {
        float lo[12], hi[12];
#pragma unroll
        for (int v = 0; v < 4; v++)
#pragma unroll
            for (int i = 0; i < 3; i++)
                unpack2(acc[v][i][q], lo[v*3 + i], hi[v*3 + i]);

#pragma unroll
        for (int h = 0; h < 2; h++) {
            const float* f = h ? hi : lo;
            int pose = pg*4 + 2*q + h;
            float* dst = out + ((size_t)pose * V + v0) * 3;
            if (vec) {
                float4* d4 = (float4*)dst;
                d4[0] = make_float4(f[0], f[1], f[2],  f[3]);
                d4[1] = make_float4(f[4], f[5], f[6],  f[7]);
                d4[2] = make_float4(f[8], f[9], f[10], f[11]);
            } else {
#pragma unroll
                for (int v = 0; v < 4; v++)
                    if (v0 + v < V) {
                        dst[v*3+0] = f[v*3+0];
                        dst[v*3+1] = f[v*3+1];
                        dst[v*3+2] = f[v*3+2];
                    }
            }
        }
    }
}

// ---------------------------------------------------------------------------
extern "C" void kernel_launch(void* const* d_in, const int* in_sizes, int n_in,
                              void* d_out, int out_size)
{
    const float* verts   = (const float*)d_in[0];   // (1, V, 3)
    const float* joints  = (const float*)d_in[1];   // (1, 23, 3)
    const float* weights = (const float*)d_in[2];   // (V, 23)
    const float* disp    = (const float*)d_in[3];   // (P, 1, 3)
    const float* rdis    = (const float*)d_in[4];   // (P, 3)

    int V = in_sizes[0] / 3;
    float* out = (float*)d_out;
    float* out_joints = out + (size_t)out_size - (size_t)NP * NJ * 3;

    pose_kernel<<<1, 32>>>(joints, disp, rdis,
                           (const float*)d_in[5],  (const float*)d_in[6],
                           (const float*)d_in[7],  (const float*)d_in[8],
                           (const float*)d_in[9],  (const float*)d_in[10],
                           (const float*)d_in[11], (const float*)d_in[12],
                           (const float*)d_in[13], (const float*)d_in[14],
                           (const float*)d_in[15],
                           out_joints);

    int blocks = (V + 255) / 256;
    lbs_kernel<<<blocks, 256>>>(verts, weights, out, V);
}

// round 4
// speedup vs baseline: 2.1800x; 1.1682x over previous
#include <cuda_runtime.h>

#define NJ 23
#define NP 16
#define BVERT 256           // vertices per block
#define WROW 264            // padded row stride (floats) for transposed weights

// Packed A' matrices written by pose_kernel, read by lbs_kernel.
// Layout: [((j*4+k)*3+i)*16 + p]  (j=joint, k=input comp x/y/z/1, i=out coord, p=pose)
__device__ __align__(16) float d_Apacked[NJ * 4 * 3 * NP];

__constant__ int c_parents[NJ] = {-1,0,1,1,3,4,5,4,7,4,9,1,11,12,13,12,15,12,17,0,19,0,21};

// ---------------------------------------------------------------------------
// Kernel 1: pose chain (tiny). One thread per pose.
// ---------------------------------------------------------------------------
__global__ void pose_kernel(const float* __restrict__ joints,
                            const float* __restrict__ displacement,
                            const float* __restrict__ random_dis,
                            const float* __restrict__ jp0,  const float* __restrict__ jp3,
                            const float* __restrict__ jp4,  const float* __restrict__ jp5,
                            const float* __restrict__ jp7,  const float* __restrict__ jp9,
                            const float* __restrict__ jp11, const float* __restrict__ jp12,
                            const float* __restrict__ jp13, const float* __restrict__ jp15,
                            const float* __restrict__ jp17,
                            float* __restrict__ out_joints)
{
    int p = threadIdx.x;
    if (p >= NP) return;

    const float Q = 0.78539816339744831f;   // pi/4
    const float H = 1.57079632679489662f;   // pi/2
    const int   slots[11]  = {0,3,4,5,7,9,11,12,13,15,17};
    const float scales[11] = {Q,H,H,Q,Q,Q,H,H,Q,Q,Q};
    const float* prm[11] = {jp0,jp3,jp4,jp5,jp7,jp9,jp11,jp12,jp13,jp15,jp17};

    float pose[NJ][3];
    for (int jt = 0; jt < NJ; jt++) { pose[jt][0] = 0.f; pose[jt][1] = 0.f; pose[jt][2] = 0.f; }
    for (int s = 0; s < 11; s++)
        for (int k = 0; k < 3; k++)
            pose[slots[s]][k] = scales[s] * tanhf(prm[s][p*3 + k]);

    float shift[3];
    for (int k = 0; k < 3; k++)
        shift[k] = random_dis[p*3 + k] + 3.0f * tanhf(displacement[p*3 + k]);

    float GR[NJ][9], Gt[NJ][3];

    for (int jt = 0; jt < NJ; jt++) {
        float rx = pose[jt][0], ry = pose[jt][1], rz = pose[jt][2];
        float ang = sqrtf(rx*rx + ry*ry + rz*rz + 1e-16f);
        float x = rx/ang, y = ry/ang, z = rz/ang;
        float sn = sinf(ang), cs = cosf(ang), t = 1.0f - cs;
        float R[9];
        R[0] = 1.0f - t*(y*y + z*z); R[1] = -sn*z + t*x*y;        R[2] =  sn*y + t*x*z;
        R[3] =  sn*z + t*x*y;        R[4] = 1.0f - t*(x*x + z*z); R[5] = -sn*x + t*y*z;
        R[6] = -sn*y + t*x*z;        R[7] =  sn*x + t*y*z;        R[8] = 1.0f - t*(x*x + y*y);

        int par = c_parents[jt];
        float rel[3];
        if (par < 0) {
            rel[0] = joints[0]; rel[1] = joints[1]; rel[2] = joints[2];
        } else {
            rel[0] = joints[jt*3+0] - joints[par*3+0];
            rel[1] = joints[jt*3+1] - joints[par*3+1];
            rel[2] = joints[jt*3+2] - joints[par*3+2];
        }

        if (par < 0) {
            for (int i = 0; i < 9; i++) GR[jt][i] = R[i];
            for (int i = 0; i < 3; i++) Gt[jt][i] = rel[i];
        } else {
            for (int i = 0; i < 3; i++) {
                for (int k = 0; k < 3; k++) {
                    GR[jt][i*3+k] = GR[par][i*3+0]*R[0*3+k]
                                  + GR[par][i*3+1]*R[1*3+k]
                                  + GR[par][i*3+2]*R[2*3+k];
                }
                Gt[jt][i] = GR[par][i*3+0]*rel[0] + GR[par][i*3+1]*rel[1]
                          + GR[par][i*3+2]*rel[2] + Gt[par][i];
            }
        }

        float jx = joints[jt*3+0], jy = joints[jt*3+1], jz = joints[jt*3+2];
        for (int i = 0; i < 3; i++) {
            out_joints[(p*NJ + jt)*3 + i] = Gt[jt][i] + shift[i];
            float At = Gt[jt][i]
                     - (GR[jt][i*3+0]*jx + GR[jt][i*3+1]*jy + GR[jt][i*3+2]*jz)
                     + shift[i];
            d_Apacked[((jt*4 + 0)*3 + i)*NP + p] = GR[jt][i*3+0];
            d_Apacked[((jt*4 + 1)*3 + i)*NP + p] = GR[jt][i*3+1];
            d_Apacked[((jt*4 + 2)*3 + i)*NP + p] = GR[jt][i*3+2];
            d_Apacked[((jt*4 + 3)*3 + i)*NP + p] = At;
        }
    }
}

// ---------------------------------------------------------------------------
// f32x2 packed helpers (SASS FFMA2 — only reachable via PTX)
// ---------------------------------------------------------------------------
__device__ __forceinline__ unsigned long long pack2(float a) {
    unsigned long long r;
    asm("mov.b64 %0, {%1, %1};" : "=l"(r) : "f"(a));
    return r;
}
__device__ __forceinline__ void fma2(unsigned long long& d, unsigned long long a, unsigned long long b) {
    asm("fma.rn.f32x2 %0, %1, %2, %0;" : "+l"(d) : "l"(a), "l"(b));
}
__device__ __forceinline__ void unpack2(unsigned long long v, float& a, float& b) {
    asm("mov.b64 {%0, %1}, %2;" : "=f"(a), "=f"(b) : "l"(v));
}

// ---------------------------------------------------------------------------
// Kernel 2: vertex skinning. Each thread: 8 vertices x 4 poses.
// tid%4 = pose group (poses 4*pg..4*pg+3), tid/4 = vertex octet within block.
// Block = 128 threads covering 256 vertices. A-slice LDS amortized over 8 verts.
// ---------------------------------------------------------------------------
__global__ void __launch_bounds__(128, 3)
lbs_kernel(const float* __restrict__ verts,
           const float* __restrict__ weights,
           float* __restrict__ out, int V)
{
    __shared__ __align__(16) float sA[NJ * 4 * 3 * NP];   // 17664 B
    __shared__ __align__(16) float sW[NJ * WROW];         // 24288 B, transposed [j][v]

    int tid = threadIdx.x;

    // Stage A (float4)
    for (int t = tid; t < NJ*4*3*NP/4; t += 128)
        ((float4*)sA)[t] = ((const float4*)d_Apacked)[t];

    // Stage weights transposed: sW[j][v] = weights[vbase+v][j]. Gmem read coalesced.
    int vbase = blockIdx.x * BVERT;
    int nv = V - vbase; if (nv > BVERT) nv = BVERT;
    for (int t = tid; t < nv * NJ; t += 128) {
        int v = t / NJ;
        int j = t - v * NJ;
        sW[j * WROW + v] = weights[(size_t)vbase * NJ + t];
    }
    __syncthreads();

    int pg  = tid & 3;        // pose group (4 poses)
    int vt  = tid >> 2;       // vertex octet index 0..31
    int v0l = vt * 8;         // local vertex base
    int v0  = vbase + v0l;
    if (v0 >= V) return;      // no syncs past this point
    bool full = (v0 + 7 < V);

    // Load 8 vertices (24 contiguous floats -> 6 LDG.128 when aligned)
    float vX[8], vY[8], vZ[8];
    if (full) {
        const float4* vp = (const float4*)(verts + (size_t)v0 * 3);
        float4 c0 = vp[0], c1 = vp[1], c2 = vp[2], c3 = vp[3], c4 = vp[4], c5 = vp[5];
        vX[0]=c0.x; vY[0]=c0.y; vZ[0]=c0.z;
        vX[1]=c0.w; vY[1]=c1.x; vZ[1]=c1.y;
        vX[2]=c1.z; vY[2]=c1.w; vZ[2]=c2.x;
        vX[3]=c2.y; vY[3]=c2.z; vZ[3]=c2.w;
        vX[4]=c3.x; vY[4]=c3.y; vZ[4]=c3.z;
        vX[5]=c3.w; vY[5]=c4.x; vZ[5]=c4.y;
        vX[6]=c4.z; vY[6]=c4.w; vZ[6]=c5.x;
        vX[7]=c5.y; vY[7]=c5.z; vZ[7]=c5.w;
    } else {
#pragma unroll
        for (int v = 0; v < 8; v++) {
            if (v0 + v < V) {
                vX[v] = verts[(size_t)(v0+v)*3 + 0];
                vY[v] = verts[(size_t)(v0+v)*3 + 1];
                vZ[v] = verts[(size_t)(v0+v)*3 + 2];
            } else { vX[v]=0.f; vY[v]=0.f; vZ[v]=0.f; }
        }
    }

    // acc[v][i][q]: output coord i of vertex v for poses (4pg+2q, 4pg+2q+1)
    unsigned long long acc[8][3][2];
#pragma unroll
    for (int v = 0; v < 8; v++)
#pragma unroll
        for (int i = 0; i < 3; i++) { acc[v][i][0] = 0ull; acc[v][i][1] = 0ull; }

    const float* sWp = sW + v0l;
    const float* Ap  = sA + pg * 4;

    for (int j = 0; j < NJ; j++) {
        float4 w4a = *(const float4*)(sWp + j * WROW);       // weights of verts 0-3
        float4 w4b = *(const float4*)(sWp + j * WROW + 4);   // verts 4-7
        float wv[8] = {w4a.x, w4a.y, w4a.z, w4a.w, w4b.x, w4b.y, w4b.z, w4b.w};
        const float* Aj = Ap + j * 4 * 3 * NP;

#pragma unroll
        for (int k = 0; k < 4; k++) {
            unsigned long long m[8];
#pragma unroll
            for (int v = 0; v < 8; v++) {
                float s = (k == 0) ? wv[v] * vX[v]
                        : (k == 1) ? wv[v] * vY[v]
                        : (k == 2) ? wv[v] * vZ[v]
                                   : wv[v];
                m[v] = pack2(s);
            }
#pragma unroll
            for (int i = 0; i < 3; i++) {
                ulonglong2 u = *(const ulonglong2*)(Aj + (k*3 + i) * NP);  // 4 poses
#pragma unroll
                for (int v = 0; v < 8; v++) {
                    fma2(acc[v][i][0], u.x, m[v]);
                    fma2(acc[v][i][1], u.y, m[v]);
                }
            }
        }
    }

    // Stores: per pose, 24 contiguous floats (8 verts x 3 coords) -> 6 STG.128
    bool vec = full;
#pragma unroll
    for (int q = 0; q < 2; q++) {
#pragma unroll
        for (int h = 0; h < 2; h++) {
            float f[24];
#pragma unroll
            for (int v = 0; v < 8; v++)
#pragma unroll
                for (int i = 0; i < 3; i++) {
                    float lo, hi;
                    unpack2(acc[v][i][q], lo, hi);
                    f[v*3 + i] = h ? hi : lo;
                }
            int pose = pg*4 + 2*q + h;
            float* dst = out + ((size_t)pose * V + v0) * 3;
            if (vec) {
                float4* d4 = (float4*)dst;
                d4[0] = make_float4(f[0],  f[1],  f[2],  f[3]);
                d4[1] = make_float4(f[4],  f[5],  f[6],  f[7]);
                d4[2] = make_float4(f[8],  f[9],  f[10], f[11]);
                d4[3] = make_float4(f[12], f[13], f[14], f[15]);
                d4[4] = make_float4(f[16], f[17], f[18], f[19]);
                d4[5] = make_float4(f[20], f[21], f[22], f[23]);
            } else {
#pragma unroll
                for (int v = 0; v < 8; v++)
                    if (v0 + v < V) {
                        dst[v*3+0] = f[v*3+0];
                        dst[v*3+1] = f[v*3+1];
                        dst[v*3+2] = f[v*3+2];
                    }
            }
        }
    }
}

// ---------------------------------------------------------------------------
extern "C" void kernel_launch(void* const* d_in, const int* in_sizes, int n_in,
                              void* d_out, int out_size)
{
    const float* verts   = (const float*)d_in[0];   // (1, V, 3)
    const float* joints  = (const float*)d_in[1];   // (1, 23, 3)
    const float* weights = (const float*)d_in[2];   // (V, 23)
    const float* disp    = (const float*)d_in[3];   // (P, 1, 3)
    const float* rdis    = (const float*)d_in[4];   // (P, 3)

    int V = in_sizes[0] / 3;
    float* out = (float*)d_out;
    float* out_joints = out + (size_t)out_size - (size_t)NP * NJ * 3;

    pose_kernel<<<1, 32>>>(joints, disp, rdis,
                           (const float*)d_in[5],  (const float*)d_in[6],
                           (const float*)d_in[7],  (const float*)d_in[8],
                           (const float*)d_in[9],  (const float*)d_in[10],
                           (const float*)d_in[11], (const float*)d_in[12],
                           (const float*)d_in[13], (const float*)d_in[14],
                           (const float*)d_in[15],
                           out_joints);

    int blocks = (V + BVERT - 1) / BVERT;
    lbs_kernel<<<blocks, 128>>>(verts, weights, out, V);
}